// round 2
// baseline (speedup 1.0000x reference)
#include <cuda_runtime.h>
#include <cuda_bf16.h>
#include <math.h>

// Problem shape (fixed by setup_inputs): x [4096, 256], y [16384, 256]
// out[i, j] = || x_i - y_j ||_2   -> [4096, 16384] fp32 row-major.
//
// Strategy: d2 = x2[i] + y2[j] - 2 * dot(x_i, y_j); out = sqrt(max(d2, 0)).
// GEMM part: classic 128x128x16 shared-memory tiled fp32 SGEMM (NT layout:
// both operands are K-contiguous row-major), 8x8 register tile per thread,
// 256 threads/block. Norms precomputed into __device__ scratch.

#define NX 4096
#define NY 16384
#define KD 256

#define BM 128
#define BN 128
#define BK 16

__device__ float g_x2[NX];
__device__ float g_y2[NY];

// One warp per row: sum of squares over 256 floats.
template <int WHICH>
__global__ void row_norms_kernel(const float* __restrict__ v, int n_rows) {
    int warps_per_block = blockDim.x >> 5;
    int row = blockIdx.x * warps_per_block + (threadIdx.x >> 5);
    if (row >= n_rows) return;
    int lane = threadIdx.x & 31;
    const float4* p = reinterpret_cast<const float4*>(v + (size_t)row * KD);
    float s = 0.0f;
    #pragma unroll
    for (int i = 0; i < 2; i++) {
        float4 t = p[lane + 32 * i];
        s += t.x * t.x + t.y * t.y + t.z * t.z + t.w * t.w;
    }
    #pragma unroll
    for (int o = 16; o > 0; o >>= 1) s += __shfl_xor_sync(0xFFFFFFFFu, s, o);
    if (lane == 0) {
        if (WHICH == 0) g_x2[row] = s;
        else            g_y2[row] = s;
    }
}

__global__ __launch_bounds__(256, 2)
void dist_kernel(const float* __restrict__ X, const float* __restrict__ Y,
                 float* __restrict__ out) {
    __shared__ float As[BK][BM];
    __shared__ float Bs[BK][BN];

    const int tid = threadIdx.x;
    const int bm = blockIdx.y * BM;
    const int bn = blockIdx.x * BN;

    // 16x16 thread grid, each thread owns an 8x8 output tile.
    const int tm = (tid >> 4) << 3;   // 0..120
    const int tn = (tid & 15) << 3;   // 0..120

    // Global->shared load mapping: thread loads one float4 per 64-row slab.
    const int lr = tid >> 2;          // 0..63
    const int lc = (tid & 3) << 2;    // 0,4,8,12

    float acc[8][8];
    #pragma unroll
    for (int i = 0; i < 8; i++)
        #pragma unroll
        for (int j = 0; j < 8; j++) acc[i][j] = 0.0f;

    const float* xp = X + (size_t)(bm + lr) * KD + lc;
    const float* yp = Y + (size_t)(bn + lr) * KD + lc;

    for (int k0 = 0; k0 < KD; k0 += BK) {
        // Load x tile [BM x BK], store transposed As[k][m]
        #pragma unroll
        for (int r = 0; r < BM; r += 64) {
            float4 t = *reinterpret_cast<const float4*>(xp + (size_t)r * KD + k0);
            As[lc + 0][lr + r] = t.x;
            As[lc + 1][lr + r] = t.y;
            As[lc + 2][lr + r] = t.z;
            As[lc + 3][lr + r] = t.w;
        }
        // Load y tile [BN x BK], store transposed Bs[k][n]
        #pragma unroll
        for (int r = 0; r < BN; r += 64) {
            float4 t = *reinterpret_cast<const float4*>(yp + (size_t)r * KD + k0);
            Bs[lc + 0][lr + r] = t.x;
            Bs[lc + 1][lr + r] = t.y;
            Bs[lc + 2][lr + r] = t.z;
            Bs[lc + 3][lr + r] = t.w;
        }
        __syncthreads();

        #pragma unroll
        for (int k = 0; k < BK; k++) {
            float a[8], b[8];
            #pragma unroll
            for (int i = 0; i < 4; i++) {
                a[i]     = As[k][tm + i];
                a[i + 4] = As[k][tm + i + 4];
            }
            #pragma unroll
            for (int j = 0; j < 4; j++) {
                b[j]     = Bs[k][tn + j];
                b[j + 4] = Bs[k][tn + j + 4];
            }
            #pragma unroll
            for (int i = 0; i < 8; i++)
                #pragma unroll
                for (int j = 0; j < 8; j++)
                    acc[i][j] = fmaf(a[i], b[j], acc[i][j]);
        }
        __syncthreads();
    }

    // Epilogue: d2 = x2 + y2 - 2*dot; out = sqrt(max(d2, 0))
    float b2[8];
    #pragma unroll
    for (int j = 0; j < 8; j++) b2[j] = g_y2[bn + tn + j];

    #pragma unroll
    for (int i = 0; i < 8; i++) {
        const int row = bm + tm + i;
        const float a2 = g_x2[row];
        float* op = out + (size_t)row * NY + bn + tn;
        #pragma unroll
        for (int j = 0; j < 8; j += 4) {
            float4 o;
            o.x = sqrtf(fmaxf(a2 + b2[j + 0] - 2.0f * acc[i][j + 0], 0.0f));
            o.y = sqrtf(fmaxf(a2 + b2[j + 1] - 2.0f * acc[i][j + 1], 0.0f));
            o.z = sqrtf(fmaxf(a2 + b2[j + 2] - 2.0f * acc[i][j + 2], 0.0f));
            o.w = sqrtf(fmaxf(a2 + b2[j + 3] - 2.0f * acc[i][j + 3], 0.0f));
            *reinterpret_cast<float4*>(op + j) = o;
        }
    }
}

extern "C" void kernel_launch(void* const* d_in, const int* in_sizes, int n_in,
                              void* d_out, int out_size) {
    const float* x = (const float*)d_in[0];   // [4096, 256]
    const float* y = (const float*)d_in[1];   // [16384, 256]
    float* out = (float*)d_out;               // [4096, 16384]

    // Row norms: 8 warps/block
    row_norms_kernel<0><<<(NX + 7) / 8, 256>>>(x, NX);
    row_norms_kernel<1><<<(NY + 7) / 8, 256>>>(y, NY);

    dim3 grid(NY / BN, NX / BM);  // (128, 32)
    dist_kernel<<<grid, 256>>>(x, y, out);
}

// round 5
// speedup vs baseline: 4.6914x; 4.6914x over previous
#include <cuda_runtime.h>
#include <cuda_bf16.h>
#include <cstdint>
#include <math.h>

// x [4096,256] fp32, y [16384,256] fp32 -> out[i,j] = ||x_i - y_j|| [4096,16384] fp32
// d2 = x2[i] + y2[j] - 2*dot(x_i,y_j); dot via mma.sync bf16 (HMMA, legal on sm_103).

#define NX 4096
#define NY 16384
#define KD 256

#define BM 128
#define BN 128
#define BK 64            // bf16 elements per K chunk (128 bytes per row)
#define KCHUNKS (KD / BK)

// ---- device scratch ----
__device__ __align__(256) __nv_bfloat16 g_xb[NX * KD];
__device__ __align__(256) __nv_bfloat16 g_yb[NY * KD];
__device__ float g_x2[NX];
__device__ float g_y2[NY];

// ---- SMEM layout ----
// [0,512)     sx2 (128 floats)
// [512,1024)  sy2 (128 floats)
// [1024, +2*32768)  2 stages x (A tile 16KB + B tile 16KB)
#define OFF_SX2   0
#define OFF_SY2   512
#define OFF_TILES 1024
#define STAGE_BYTES 32768
#define SMEM_TOTAL (OFF_TILES + 2 * STAGE_BYTES)   // 66560

__device__ __forceinline__ uint32_t smem_u32(const void* p) {
    uint32_t a;
    asm("{ .reg .u64 t; cvta.to.shared.u64 t, %1; cvt.u32.u64 %0, t; }" : "=r"(a) : "l"(p));
    return a;
}
__device__ __forceinline__ uint32_t swz(uint32_t off) {   // SW128: XOR bits[6:4] with bits[9:7]
    return off ^ ((off >> 3) & 0x70);
}
#define CP16(dst, src) asm volatile("cp.async.cg.shared.global [%0], [%1], 16;" :: "r"(dst), "l"(src) : "memory")
#define CP_COMMIT()    asm volatile("cp.async.commit_group;" ::: "memory")
#define CP_WAIT1()     asm volatile("cp.async.wait_group 1;" ::: "memory")

__device__ __forceinline__ void ldmx4(uint32_t* r, uint32_t addr) {
    asm volatile("ldmatrix.sync.aligned.m8n8.x4.shared.b16 {%0,%1,%2,%3}, [%4];"
        : "=r"(r[0]), "=r"(r[1]), "=r"(r[2]), "=r"(r[3]) : "r"(addr));
}
__device__ __forceinline__ void mma16816(float* c, const uint32_t* a, uint32_t b0, uint32_t b1) {
    asm volatile("mma.sync.aligned.m16n8k16.row.col.f32.bf16.bf16.f32 "
        "{%0,%1,%2,%3}, {%4,%5,%6,%7}, {%8,%9}, {%0,%1,%2,%3};"
        : "+f"(c[0]), "+f"(c[1]), "+f"(c[2]), "+f"(c[3])
        : "r"(a[0]), "r"(a[1]), "r"(a[2]), "r"(a[3]), "r"(b0), "r"(b1));
}

// ---- conversion + row-norm kernel (warp per row) ----
template <int WHICH>
__global__ void convert_norm_kernel(const float* __restrict__ src, int n_rows) {
    int row = blockIdx.x * (blockDim.x >> 5) + (threadIdx.x >> 5);
    if (row >= n_rows) return;
    int lane = threadIdx.x & 31;
    const float4* p = reinterpret_cast<const float4*>(src + (size_t)row * KD);
    float4 a = p[lane * 2];
    float4 b = p[lane * 2 + 1];
    float s = a.x * a.x + a.y * a.y + a.z * a.z + a.w * a.w
            + b.x * b.x + b.y * b.y + b.z * b.z + b.w * b.w;
    __nv_bfloat162 h0 = __float22bfloat162_rn(make_float2(a.x, a.y));
    __nv_bfloat162 h1 = __float22bfloat162_rn(make_float2(a.z, a.w));
    __nv_bfloat162 h2 = __float22bfloat162_rn(make_float2(b.x, b.y));
    __nv_bfloat162 h3 = __float22bfloat162_rn(make_float2(b.z, b.w));
    uint4 u;
    u.x = reinterpret_cast<unsigned&>(h0);
    u.y = reinterpret_cast<unsigned&>(h1);
    u.z = reinterpret_cast<unsigned&>(h2);
    u.w = reinterpret_cast<unsigned&>(h3);
    __nv_bfloat16* dst = (WHICH == 0) ? g_xb : g_yb;
    reinterpret_cast<uint4*>(dst + (size_t)row * KD)[lane] = u;
    #pragma unroll
    for (int o = 16; o > 0; o >>= 1) s += __shfl_xor_sync(0xFFFFFFFFu, s, o);
    if (lane == 0) {
        if (WHICH == 0) g_x2[row] = s;
        else            g_y2[row] = s;
    }
}

// ---- main bf16 HMMA distance kernel ----
__global__ __launch_bounds__(256, 2)
void dist_mma_kernel(float* __restrict__ out) {
    extern __shared__ char smem[];
    const uint32_t sb = smem_u32(smem);
    const int tid = threadIdx.x;
    const int lane = tid & 31;
    const int wid = tid >> 5;
    const int warp_m = wid >> 2;          // 0..1  -> 64-row slab
    const int warp_n = wid & 3;           // 0..3  -> 32-col slab
    const int bm = blockIdx.y * BM;
    const int bn = blockIdx.x * BN;

    float* sx2 = reinterpret_cast<float*>(smem + OFF_SX2);
    float* sy2 = reinterpret_cast<float*>(smem + OFF_SY2);
    if (tid < 128) sx2[tid] = g_x2[bm + tid];
    else           sy2[tid - 128] = g_y2[bn + tid - 128];

    // ---- global -> smem prefetch of one K chunk into one stage ----
    const int lrow  = tid >> 1;            // 0..127
    const int lhalf = (tid & 1) * 64;      // byte offset within 128B row
    const char* xsrc = reinterpret_cast<const char*>(g_xb) + (size_t)(bm + lrow) * (KD * 2) + lhalf;
    const char* ysrc = reinterpret_cast<const char*>(g_yb) + (size_t)(bn + lrow) * (KD * 2) + lhalf;
    uint32_t rowbase = (uint32_t)lrow * 128 + (uint32_t)lhalf;

    auto prefetch = [&](int chunk, int stage) {
        uint32_t sA = sb + OFF_TILES + stage * STAGE_BYTES;
        uint32_t sB = sA + 16384;
        const char* xs = xsrc + chunk * 128;
        const char* ys = ysrc + chunk * 128;
        #pragma unroll
        for (int i = 0; i < 4; i++) {
            uint32_t sw = swz(rowbase + i * 16);
            CP16(sA + sw, xs + i * 16);
            CP16(sB + sw, ys + i * 16);
        }
    };

    prefetch(0, 0); CP_COMMIT();
    prefetch(1, 1); CP_COMMIT();

    float acc[4][4][4];
    #pragma unroll
    for (int i = 0; i < 4; i++)
        #pragma unroll
        for (int j = 0; j < 4; j++)
            #pragma unroll
            for (int k = 0; k < 4; k++) acc[i][j][k] = 0.0f;

    // ldmatrix lane-address components (row = base + (lane&15), col8 = (lane>>4)*16B)
    const uint32_t lrow16 = (uint32_t)(lane & 15);
    const uint32_t lkoff  = (uint32_t)((lane >> 4) << 4);

    #pragma unroll
    for (int c = 0; c < KCHUNKS; c++) {
        CP_WAIT1();
        __syncthreads();
        const int stage = c & 1;
        uint32_t sA = sb + OFF_TILES + stage * STAGE_BYTES;
        uint32_t sB = sA + 16384;

        #pragma unroll
        for (int ks = 0; ks < 4; ks++) {           // 4 k16 steps per 64-chunk
            const uint32_t kb = ks * 32 + lkoff;   // byte offset in row
            uint32_t a[4][4];
            #pragma unroll
            for (int mm = 0; mm < 4; mm++) {
                uint32_t row = warp_m * 64 + mm * 16 + lrow16;
                ldmx4(a[mm], sA + swz(row * 128 + kb));
            }
            uint32_t b[2][4];
            #pragma unroll
            for (int np = 0; np < 2; np++) {
                uint32_t row = warp_n * 32 + np * 16 + lrow16;
                ldmx4(b[np], sB + swz(row * 128 + kb));
            }
            #pragma unroll
            for (int mm = 0; mm < 4; mm++)
                #pragma unroll
                for (int nn = 0; nn < 4; nn++) {
                    const int np = nn >> 1, hi = nn & 1;
                    mma16816(acc[mm][nn], a[mm], b[np][hi ? 1 : 0], b[np][hi ? 3 : 2]);
                }
        }
        __syncthreads();
        if (c + 2 < KCHUNKS) prefetch(c + 2, stage);
        CP_COMMIT();
    }

    // ---- epilogue: d = sqrt(max(x2 + y2 - 2*acc, 0)) ----
    const int t4 = lane >> 2;        // 0..7
    const int tc = (lane & 3) * 2;   // 0,2,4,6
    #pragma unroll
    for (int mm = 0; mm < 4; mm++) {
        const int r0 = warp_m * 64 + mm * 16 + t4;
        const float x2a = sx2[r0];
        const float x2b = sx2[r0 + 8];
        float* orow0 = out + (size_t)(bm + r0) * NY + bn;
        float* orow1 = orow0 + (size_t)8 * NY;
        #pragma unroll
        for (int nn = 0; nn < 4; nn++) {
            const int col = warp_n * 32 + nn * 8 + tc;
            const float y2a = sy2[col];
            const float y2b = sy2[col + 1];
            float d0 = fmaxf(fmaf(-2.0f, acc[mm][nn][0], x2a + y2a), 0.0f);
            float d1 = fmaxf(fmaf(-2.0f, acc[mm][nn][1], x2a + y2b), 0.0f);
            float d2 = fmaxf(fmaf(-2.0f, acc[mm][nn][2], x2b + y2a), 0.0f);
            float d3 = fmaxf(fmaf(-2.0f, acc[mm][nn][3], x2b + y2b), 0.0f);
            float2 o0, o1;
            asm("sqrt.approx.f32 %0, %1;" : "=f"(o0.x) : "f"(d0));
            asm("sqrt.approx.f32 %0, %1;" : "=f"(o0.y) : "f"(d1));
            asm("sqrt.approx.f32 %0, %1;" : "=f"(o1.x) : "f"(d2));
            asm("sqrt.approx.f32 %0, %1;" : "=f"(o1.y) : "f"(d3));
            *reinterpret_cast<float2*>(orow0 + col) = o0;
            *reinterpret_cast<float2*>(orow1 + col) = o1;
        }
    }
}

extern "C" void kernel_launch(void* const* d_in, const int* in_sizes, int n_in,
                              void* d_out, int out_size) {
    const float* x = (const float*)d_in[0];   // [4096, 256]
    const float* y = (const float*)d_in[1];   // [16384, 256]
    float* out = (float*)d_out;               // [4096, 16384]

    convert_norm_kernel<0><<<NX / 8, 256>>>(x, NX);
    convert_norm_kernel<1><<<NY / 8, 256>>>(y, NY);

    cudaFuncSetAttribute(dist_mma_kernel, cudaFuncAttributeMaxDynamicSharedMemorySize, SMEM_TOTAL);
    dim3 grid(NY / BN, NX / BM);  // (128, 32)
    dist_mma_kernel<<<grid, 256, SMEM_TOTAL>>>(out);
}